// round 1
// baseline (speedup 1.0000x reference)
#include <cuda_runtime.h>
#include <math.h>

#define BATCH 16
#define DIMC  512
#define RES   1024
#define NHKD  256
#define HQKV  1536
#define DHDIM 1024
#define NHEAD 8
#define KD    32
#define DV    128
#define ATT_SCALE 0.17677669529663687f

// ---------------- scratch (static device globals; no allocations) -------------
__device__ float g_qkv[BATCH * HQKV * RES];   // 100.7 MB
__device__ float g_q  [BATCH * NHKD * RES];   // 16.8 MB
__device__ float g_att[BATCH * DHDIM * RES];  // 67 MB

// ---------------- GEMM (C[b,o,l] = sum_c W[o,c] * X[b,c,l]) + BN ---------------
// 128x128 tile, BK=8, 256 threads, 8x8 microtile, float4 smem reads.
__global__ __launch_bounds__(256) void gemm_bn_kernel(
    const float* __restrict__ W, const float* __restrict__ X,
    const float* __restrict__ gg, const float* __restrict__ bb,
    const float* __restrict__ mm, const float* __restrict__ vv,
    float* __restrict__ out, int O, int C, int L)
{
    __shared__ float As[8][128];
    __shared__ float Bs[8][128];

    const int b  = blockIdx.z;
    const float* Xb = X + (size_t)b * C * L;
    float* Ob = out + (size_t)b * O * L;
    const int o0 = blockIdx.y * 128;
    const int l0 = blockIdx.x * 128;
    const int t  = threadIdx.x;
    const int tx = t & 15, ty = t >> 4;

    float acc[8][8];
    #pragma unroll
    for (int i = 0; i < 8; i++)
        #pragma unroll
        for (int j = 0; j < 8; j++) acc[i][j] = 0.0f;

    const int ao = t >> 1, ac = (t & 1) * 4;     // A tile: 128 rows x 8 k
    const int bc = t >> 5, bl = (t & 31) * 4;    // B tile: 8 k x 128 l

    for (int k0 = 0; k0 < C; k0 += 8) {
        float4 a = *(const float4*)&W[(size_t)(o0 + ao) * C + k0 + ac];
        As[ac + 0][ao] = a.x; As[ac + 1][ao] = a.y;
        As[ac + 2][ao] = a.z; As[ac + 3][ao] = a.w;
        *(float4*)&Bs[bc][bl] = *(const float4*)&Xb[(size_t)(k0 + bc) * L + l0 + bl];
        __syncthreads();

        #pragma unroll
        for (int k = 0; k < 8; k++) {
            float av[8], bv[8];
            *(float4*)&av[0] = *(const float4*)&As[k][ty * 8];
            *(float4*)&av[4] = *(const float4*)&As[k][ty * 8 + 4];
            *(float4*)&bv[0] = *(const float4*)&Bs[k][tx * 8];
            *(float4*)&bv[4] = *(const float4*)&Bs[k][tx * 8 + 4];
            #pragma unroll
            for (int i = 0; i < 8; i++)
                #pragma unroll
                for (int j = 0; j < 8; j++)
                    acc[i][j] = fmaf(av[i], bv[j], acc[i][j]);
        }
        __syncthreads();
    }

    #pragma unroll
    for (int i = 0; i < 8; i++) {
        int o = o0 + ty * 8 + i;
        float inv  = gg[o] * rsqrtf(vv[o] + 1e-5f);
        float beta = bb[o] - mm[o] * inv;
        float4 r0, r1;
        r0.x = fmaf(acc[i][0], inv, beta); r0.y = fmaf(acc[i][1], inv, beta);
        r0.z = fmaf(acc[i][2], inv, beta); r0.w = fmaf(acc[i][3], inv, beta);
        r1.x = fmaf(acc[i][4], inv, beta); r1.y = fmaf(acc[i][5], inv, beta);
        r1.z = fmaf(acc[i][6], inv, beta); r1.w = fmaf(acc[i][7], inv, beta);
        *(float4*)&Ob[(size_t)o * L + l0 + tx * 8]     = r0;
        *(float4*)&Ob[(size_t)o * L + l0 + tx * 8 + 4] = r1;
    }
}

// ---------------- depthwise conv (k=3, pad=1) + BN on q channels ----------------
__global__ __launch_bounds__(256) void dwconv_bn_kernel(
    const float* __restrict__ qkv, const float* __restrict__ wdw,
    const float* __restrict__ gg, const float* __restrict__ bb,
    const float* __restrict__ mm, const float* __restrict__ vv,
    float* __restrict__ outq)
{
    int idx = blockIdx.x * blockDim.x + threadIdx.x;   // B*256*1024
    int l  = idx & (RES - 1);
    int ch = (idx >> 10) & (NHKD - 1);
    int b  = idx >> 18;
    const float* row = qkv + ((size_t)b * HQKV + ch) * RES;
    float x0 = (l > 0)       ? row[l - 1] : 0.0f;
    float x1 = row[l];
    float x2 = (l < RES - 1) ? row[l + 1] : 0.0f;
    float y = x0 * wdw[ch * 3] + x1 * wdw[ch * 3 + 1] + x2 * wdw[ch * 3 + 2];
    float inv = gg[ch] * rsqrtf(vv[ch] + 1e-5f);
    outq[idx] = (y - mm[ch]) * inv + bb[ch];
}

// ---------------- fused attention: logits+bias -> softmax -> p@v -> relu -------
// One block handles (b, h, 32-row n tile). smem holds q tile, full 32x1024 logits,
// and a 128x128 k/v staging tile. 256 threads.
#define NT 32
#define MT 128
#define S_STRIDE 1028
#define V_STRIDE 132
#define Q_OFF    0
#define S_OFF    (32 * 33)
#define VS_OFF   (S_OFF + 32 * S_STRIDE)
#define DSUM_OFF (VS_OFF + 128 * V_STRIDE)
#define ATTN_SMEM_FLOATS (DSUM_OFF + 32)
#define ATTN_SMEM_BYTES  (ATTN_SMEM_FLOATS * 4)

__global__ __launch_bounds__(256) void attn_kernel(
    const float* __restrict__ qbuf, const float* __restrict__ qkv,
    const float* __restrict__ bias, float* __restrict__ outp)
{
    extern __shared__ __align__(16) float sh[];
    float* q_s  = sh + Q_OFF;     // [32 n][33]   (n-major, d index, padded)
    float* s_s  = sh + S_OFF;     // [32 n][1028]
    float* vs   = sh + VS_OFF;    // [128][132] (also k staging [32][128])
    float* dsum = sh + DSUM_OFF;  // [32]

    const int b = blockIdx.z, h = blockIdx.y;
    const int n0 = blockIdx.x * NT;
    const int t = threadIdx.x;

    const float* qb = qbuf + ((size_t)b * NHKD + h * KD) * RES;
    const float* kb = qkv + ((size_t)b * HQKV + NHKD + h * KD) * RES;
    const float* vb = qkv + ((size_t)b * HQKV + 2 * NHKD + h * DV) * RES;
    const float* ab = bias + h * RES;

    // load q tile: q_s[n][d]
    for (int i = t; i < KD * NT; i += 256) {
        int d = i >> 5, nn = i & 31;
        q_s[nn * 33 + d] = qb[d * RES + n0 + nn];
    }
    __syncthreads();

    // ---- phase 2: logits s[n][m] = scale * q.k + bias(|n-m|) ----
    const int pn = t >> 3;        // 0..31 row
    const int mlane = t & 7;      // 0..7
    const int ng = n0 + pn;
    for (int mt = 0; mt < RES; mt += MT) {
        // stage k tile: ks[d][m'] (reuse vs area, stride 128)
        for (int i = t * 4; i < KD * MT; i += 1024) {
            int d = i >> 7, mq = i & 127;
            *(float4*)&vs[d * MT + mq] = *(const float4*)&kb[d * RES + mt + mq];
        }
        __syncthreads();
        float acc[16];
        #pragma unroll
        for (int j = 0; j < 16; j++) acc[j] = 0.0f;
        #pragma unroll
        for (int d = 0; d < KD; d++) {
            float qv = q_s[pn * 33 + d];
            #pragma unroll
            for (int j = 0; j < 16; j++)
                acc[j] = fmaf(qv, vs[d * MT + mlane + j * 8], acc[j]);
        }
        #pragma unroll
        for (int j = 0; j < 16; j++) {
            int m = mt + mlane + j * 8;
            int dd = ng - m; if (dd < 0) dd = -dd;
            s_s[pn * S_STRIDE + m] = fmaf(acc[j], ATT_SCALE, ab[dd]);
        }
        __syncthreads();
    }

    // ---- phase 3: softmax per row (8 warps x 4 rows) ----
    {
        int warp = t >> 5, lane = t & 31;
        for (int r = warp; r < NT; r += 8) {
            float* row = s_s + r * S_STRIDE;
            float mx = -1e30f;
            for (int i = lane; i < RES; i += 32) mx = fmaxf(mx, row[i]);
            #pragma unroll
            for (int o = 16; o; o >>= 1) mx = fmaxf(mx, __shfl_xor_sync(0xffffffffu, mx, o));
            float sum = 0.0f;
            for (int i = lane; i < RES; i += 32) {
                float e = __expf(row[i] - mx);
                row[i] = e;
                sum += e;
            }
            #pragma unroll
            for (int o = 16; o; o >>= 1) sum += __shfl_xor_sync(0xffffffffu, sum, o);
            if (lane == 0) dsum[r] = 1.0f / sum;
        }
    }
    __syncthreads();

    // ---- phase 4: out[d][n] = sum_m v[d][m] * p[n][m]  (smem-tiled) ----
    const int td = t & 63;   // 2 d-rows per thread
    const int tn = t >> 6;   // 8 n-cols per thread
    float o_acc[2][8];
    #pragma unroll
    for (int i = 0; i < 2; i++)
        #pragma unroll
        for (int j = 0; j < 8; j++) o_acc[i][j] = 0.0f;

    for (int mt = 0; mt < RES; mt += MT) {
        for (int i = t * 4; i < DV * MT; i += 1024) {
            int d = i >> 7, mq = i & 127;
            *(float4*)&vs[d * V_STRIDE + mq] = *(const float4*)&vb[d * RES + mt + mq];
        }
        __syncthreads();
        #pragma unroll 2
        for (int m4 = 0; m4 < MT; m4 += 4) {
            float4 v0 = *(const float4*)&vs[(td * 2)     * V_STRIDE + m4];
            float4 v1 = *(const float4*)&vs[(td * 2 + 1) * V_STRIDE + m4];
            #pragma unroll
            for (int j = 0; j < 8; j++) {
                float4 p = *(const float4*)&s_s[(tn * 8 + j) * S_STRIDE + mt + m4];
                o_acc[0][j] = fmaf(v0.x, p.x, fmaf(v0.y, p.y, fmaf(v0.z, p.z, fmaf(v0.w, p.w, o_acc[0][j]))));
                o_acc[1][j] = fmaf(v1.x, p.x, fmaf(v1.y, p.y, fmaf(v1.z, p.z, fmaf(v1.w, p.w, o_acc[1][j]))));
            }
        }
        __syncthreads();
    }

    // stage relu(out/denom) into smem (stride 36 keeps float4 alignment), then
    // write coalesced rows of 32 floats.
    #pragma unroll
    for (int i = 0; i < 2; i++) {
        int d = td * 2 + i;
        #pragma unroll
        for (int j = 0; j < 8; j++) {
            int nn = tn * 8 + j;
            vs[d * 36 + nn] = fmaxf(o_acc[i][j] * dsum[nn], 0.0f);
        }
    }
    __syncthreads();
    float* ob = outp + ((size_t)b * DHDIM + h * DV) * RES + n0;
    for (int i = t; i < DV * 8; i += 256) {
        int d = i >> 3, q4 = (i & 7) * 4;
        *(float4*)&ob[(size_t)d * RES + q4] = *(const float4*)&vs[d * 36 + q4];
    }
}

// --------------------------------- launch -------------------------------------
extern "C" void kernel_launch(void* const* d_in, const int* in_sizes, int n_in,
                              void* d_out, int out_size)
{
    const float* x      = (const float*)d_in[0];
    const float* w_qkv  = (const float*)d_in[1];
    const float* qkv_g  = (const float*)d_in[2];
    const float* qkv_b  = (const float*)d_in[3];
    const float* qkv_m  = (const float*)d_in[4];
    const float* qkv_v  = (const float*)d_in[5];
    const float* w_dw   = (const float*)d_in[6];
    const float* dw_g   = (const float*)d_in[7];
    const float* dw_b   = (const float*)d_in[8];
    const float* dw_m   = (const float*)d_in[9];
    const float* dw_v   = (const float*)d_in[10];
    const float* w_proj = (const float*)d_in[11];
    const float* proj_g = (const float*)d_in[12];
    const float* proj_b = (const float*)d_in[13];
    const float* proj_m = (const float*)d_in[14];
    const float* proj_v = (const float*)d_in[15];
    const float* att_bias = (const float*)d_in[16];
    // d_in[17] = bias_idxs (== |n-m|, computed inline)

    float *p_qkv, *p_q, *p_att;
    cudaGetSymbolAddress((void**)&p_qkv, g_qkv);
    cudaGetSymbolAddress((void**)&p_q,   g_q);
    cudaGetSymbolAddress((void**)&p_att, g_att);

    cudaFuncSetAttribute(attn_kernel, cudaFuncAttributeMaxDynamicSharedMemorySize,
                         ATTN_SMEM_BYTES);

    // 1) QKV GEMM + BN : (1536 x 512) x (512 x 1024) per batch
    gemm_bn_kernel<<<dim3(RES / 128, HQKV / 128, BATCH), 256>>>(
        w_qkv, x, qkv_g, qkv_b, qkv_m, qkv_v, p_qkv, HQKV, DIMC, RES);

    // 2) depthwise conv + BN on q
    dwconv_bn_kernel<<<(BATCH * NHKD * RES) / 256, 256>>>(
        p_qkv, w_dw, dw_g, dw_b, dw_m, dw_v, p_q);

    // 3) fused attention (logits+bias, softmax, p@v, relu)
    attn_kernel<<<dim3(RES / NT, NHEAD, BATCH), 256, ATTN_SMEM_BYTES>>>(
        p_q, p_qkv, att_bias, p_att);

    // 4) projection GEMM + BN : (512 x 1024) x (1024 x 1024) per batch
    gemm_bn_kernel<<<dim3(RES / 128, DIMC / 128, BATCH), 256>>>(
        w_proj, p_att, proj_g, proj_b, proj_m, proj_v, (float*)d_out,
        DIMC, DHDIM, RES);
}

// round 3
// speedup vs baseline: 1.3929x; 1.3929x over previous
#include <cuda_runtime.h>
#include <math.h>

#define BATCH 16
#define DIMC  512
#define RES   1024
#define NHKD  256
#define HQKV  1536
#define DHDIM 1024
#define NHEAD 8
#define KD    32
#define DV    128
#define ATT_SCALE 0.17677669529663687f

// ---------------- scratch (static device globals; no allocations) -------------
__device__ float g_qkv[BATCH * HQKV * RES];   // 100.7 MB
__device__ float g_q  [BATCH * NHKD * RES];   // 16.8 MB
__device__ float g_att[BATCH * DHDIM * RES];  // 67 MB

// ---------------- GEMM (C[b,o,l] = sum_c W[o,c] * X[b,c,l]) + BN ---------------
// 128x128 tile, BK=8, 128 threads, 16x8 microtile, double-buffered smem.
__global__ __launch_bounds__(128) void gemm_bn_kernel(
    const float* __restrict__ W, const float* __restrict__ X,
    const float* __restrict__ gg, const float* __restrict__ bb,
    const float* __restrict__ mm, const float* __restrict__ vv,
    float* __restrict__ out, int O, int C, int L)
{
    __shared__ float As[2][8][128];
    __shared__ float Bs[2][8][128];

    const int b  = blockIdx.z;
    const float* Xb = X + (size_t)b * C * L;
    float* Ob = out + (size_t)b * O * L;
    const int o0 = blockIdx.y * 128;
    const int l0 = blockIdx.x * 128;
    const int t  = threadIdx.x;
    const int og = t >> 4;                  // 0..7  -> 16 output rows each
    const int lg = t & 15;                  // 0..15 -> 2x float4 output cols

    float acc[16][8];
    #pragma unroll
    for (int i = 0; i < 16; i++)
        #pragma unroll
        for (int j = 0; j < 8; j++) acc[i][j] = 0.0f;

    // staging regs
    float4 ra0, ra1, rb0, rb1;
    const int bk0 = t >> 5;                 // 0..3
    const int bl4 = (t & 31) * 4;           // 0..124

    // prime tile 0
    {
        const float* wr = &W[(size_t)(o0 + t) * C];
        ra0 = *(const float4*)&wr[0];
        ra1 = *(const float4*)&wr[4];
        rb0 = *(const float4*)&Xb[(size_t)bk0 * L + l0 + bl4];
        rb1 = *(const float4*)&Xb[(size_t)(bk0 + 4) * L + l0 + bl4];
        As[0][0][t] = ra0.x; As[0][1][t] = ra0.y; As[0][2][t] = ra0.z; As[0][3][t] = ra0.w;
        As[0][4][t] = ra1.x; As[0][5][t] = ra1.y; As[0][6][t] = ra1.z; As[0][7][t] = ra1.w;
        *(float4*)&Bs[0][bk0][bl4]     = rb0;
        *(float4*)&Bs[0][bk0 + 4][bl4] = rb1;
    }
    __syncthreads();

    int buf = 0;
    for (int k0 = 0; k0 < C; k0 += 8) {
        const bool more = (k0 + 8 < C);
        if (more) {
            const float* wr = &W[(size_t)(o0 + t) * C + k0 + 8];
            ra0 = *(const float4*)&wr[0];
            ra1 = *(const float4*)&wr[4];
            rb0 = *(const float4*)&Xb[(size_t)(k0 + 8 + bk0) * L + l0 + bl4];
            rb1 = *(const float4*)&Xb[(size_t)(k0 + 12 + bk0) * L + l0 + bl4];
        }
        #pragma unroll
        for (int k = 0; k < 8; k++) {
            float av[16], bv[8];
            *(float4*)&av[0]  = *(const float4*)&As[buf][k][og * 16];
            *(float4*)&av[4]  = *(const float4*)&As[buf][k][og * 16 + 4];
            *(float4*)&av[8]  = *(const float4*)&As[buf][k][og * 16 + 8];
            *(float4*)&av[12] = *(const float4*)&As[buf][k][og * 16 + 12];
            *(float4*)&bv[0]  = *(const float4*)&Bs[buf][k][lg * 4];
            *(float4*)&bv[4]  = *(const float4*)&Bs[buf][k][lg * 4 + 64];
            #pragma unroll
            for (int i = 0; i < 16; i++)
                #pragma unroll
                for (int j = 0; j < 8; j++)
                    acc[i][j] = fmaf(av[i], bv[j], acc[i][j]);
        }
        if (more) {
            int nb = buf ^ 1;
            As[nb][0][t] = ra0.x; As[nb][1][t] = ra0.y; As[nb][2][t] = ra0.z; As[nb][3][t] = ra0.w;
            As[nb][4][t] = ra1.x; As[nb][5][t] = ra1.y; As[nb][6][t] = ra1.z; As[nb][7][t] = ra1.w;
            *(float4*)&Bs[nb][bk0][bl4]     = rb0;
            *(float4*)&Bs[nb][bk0 + 4][bl4] = rb1;
        }
        __syncthreads();
        buf ^= 1;
    }

    #pragma unroll
    for (int i = 0; i < 16; i++) {
        int o = o0 + og * 16 + i;
        float inv  = gg[o] * rsqrtf(vv[o] + 1e-5f);
        float beta = bb[o] - mm[o] * inv;
        float4 r0, r1;
        r0.x = fmaf(acc[i][0], inv, beta); r0.y = fmaf(acc[i][1], inv, beta);
        r0.z = fmaf(acc[i][2], inv, beta); r0.w = fmaf(acc[i][3], inv, beta);
        r1.x = fmaf(acc[i][4], inv, beta); r1.y = fmaf(acc[i][5], inv, beta);
        r1.z = fmaf(acc[i][6], inv, beta); r1.w = fmaf(acc[i][7], inv, beta);
        *(float4*)&Ob[(size_t)o * L + l0 + lg * 4]      = r0;
        *(float4*)&Ob[(size_t)o * L + l0 + 64 + lg * 4] = r1;
    }
}

// ---------------- depthwise conv (k=3, pad=1) + BN on q channels ----------------
__global__ __launch_bounds__(256) void dwconv_bn_kernel(
    const float* __restrict__ qkv, const float* __restrict__ wdw,
    const float* __restrict__ gg, const float* __restrict__ bb,
    const float* __restrict__ mm, const float* __restrict__ vv,
    float* __restrict__ outq)
{
    int idx = blockIdx.x * blockDim.x + threadIdx.x;   // B*256*1024
    int l  = idx & (RES - 1);
    int ch = (idx >> 10) & (NHKD - 1);
    int b  = idx >> 18;
    const float* row = qkv + ((size_t)b * HQKV + ch) * RES;
    float x0 = (l > 0)       ? row[l - 1] : 0.0f;
    float x1 = row[l];
    float x2 = (l < RES - 1) ? row[l + 1] : 0.0f;
    float y = x0 * wdw[ch * 3] + x1 * wdw[ch * 3 + 1] + x2 * wdw[ch * 3 + 2];
    float inv = gg[ch] * rsqrtf(vv[ch] + 1e-5f);
    outq[idx] = (y - mm[ch]) * inv + bb[ch];
}

// ---------------- fused attention: logits+bias -> softmax -> p@v -> relu -------
// 512 threads; block = (b, h, 32-row n tile). smem: q tile, bias row, full
// 32x1024 logits, 128x128 k/v staging.
#define NT 32
#define Q_OFF    0                       // [32][33]
#define BIAS_OFF 1056                    // [1024]
#define DSUM_OFF 2080                    // [32]
#define VS_OFF   2112                    // 128*132 = 16896 (also k: 32*260=8320)
#define S_OFF    (VS_OFF + 16896)        // [32][1028]
#define ATTN_SMEM_FLOATS (S_OFF + 32 * 1028)
#define ATTN_SMEM_BYTES  (ATTN_SMEM_FLOATS * 4)

__global__ __launch_bounds__(512) void attn_kernel(
    const float* __restrict__ qbuf, const float* __restrict__ qkv,
    const float* __restrict__ bias, float* __restrict__ outp)
{
    extern __shared__ __align__(16) float sh[];
    float* q_s    = sh + Q_OFF;
    float* bias_s = sh + BIAS_OFF;
    float* dsum   = sh + DSUM_OFF;
    float* vs     = sh + VS_OFF;
    float* s_s    = sh + S_OFF;

    const int b = blockIdx.z, h = blockIdx.y;
    const int n0 = blockIdx.x * NT;
    const int t = threadIdx.x;
    const int lane = t & 31, wrp = t >> 5;

    const float* qb = qbuf + ((size_t)b * NHKD + h * KD) * RES;
    const float* kb = qkv + ((size_t)b * HQKV + NHKD + h * KD) * RES;
    const float* vb = qkv + ((size_t)b * HQKV + 2 * NHKD + h * DV) * RES;
    const float* ab = bias + h * RES;

    // load q tile (n-major) and bias row
    for (int i = t; i < KD * NT; i += 512) {
        int d = i >> 5, nn = i & 31;
        q_s[nn * 33 + d] = qb[d * RES + n0 + nn];
    }
    for (int i = t; i < RES; i += 512) bias_s[i] = ab[i];
    __syncthreads();

    // ---- phase 2: logits s[n][m] = scale*q.k + bias(|n-m|). m-tile = 256 ----
    const int c0  = lane * 4;
    const int n_a = wrp * 2, n_b = n_a + 1;
    const int ng_a = n0 + n_a, ng_b = n0 + n_b;
    for (int mt = 0; mt < RES; mt += 256) {
        // stage k tile [32 d][256 m], stride 260
        for (int s = t; s < 2048; s += 512) {
            int d = s >> 6, m4 = (s & 63) * 4;
            *(float4*)&vs[d * 260 + m4] = *(const float4*)&kb[d * RES + mt + m4];
        }
        __syncthreads();

        float4 a00 = {0,0,0,0}, a01 = {0,0,0,0}, a10 = {0,0,0,0}, a11 = {0,0,0,0};
        #pragma unroll
        for (int d = 0; d < KD; d++) {
            float qa = q_s[n_a * 33 + d];
            float qbv = q_s[n_b * 33 + d];
            float4 k0 = *(const float4*)&vs[d * 260 + c0];
            float4 k1 = *(const float4*)&vs[d * 260 + 128 + c0];
            a00.x = fmaf(qa, k0.x, a00.x); a00.y = fmaf(qa, k0.y, a00.y);
            a00.z = fmaf(qa, k0.z, a00.z); a00.w = fmaf(qa, k0.w, a00.w);
            a01.x = fmaf(qa, k1.x, a01.x); a01.y = fmaf(qa, k1.y, a01.y);
            a01.z = fmaf(qa, k1.z, a01.z); a01.w = fmaf(qa, k1.w, a01.w);
            a10.x = fmaf(qbv, k0.x, a10.x); a10.y = fmaf(qbv, k0.y, a10.y);
            a10.z = fmaf(qbv, k0.z, a10.z); a10.w = fmaf(qbv, k0.w, a10.w);
            a11.x = fmaf(qbv, k1.x, a11.x); a11.y = fmaf(qbv, k1.y, a11.y);
            a11.z = fmaf(qbv, k1.z, a11.z); a11.w = fmaf(qbv, k1.w, a11.w);
        }
        {
            int m0 = mt + c0, m1 = mt + 128 + c0;
            float4 r;
            r.x = fmaf(a00.x, ATT_SCALE, bias_s[abs(ng_a - (m0 + 0))]);
            r.y = fmaf(a00.y, ATT_SCALE, bias_s[abs(ng_a - (m0 + 1))]);
            r.z = fmaf(a00.z, ATT_SCALE, bias_s[abs(ng_a - (m0 + 2))]);
            r.w = fmaf(a00.w, ATT_SCALE, bias_s[abs(ng_a - (m0 + 3))]);
            *(float4*)&s_s[n_a * 1028 + m0] = r;
            r.x = fmaf(a01.x, ATT_SCALE, bias_s[abs(ng_a - (m1 + 0))]);
            r.y = fmaf(a01.y, ATT_SCALE, bias_s[abs(ng_a - (m1 + 1))]);
            r.z = fmaf(a01.z, ATT_SCALE, bias_s[abs(ng_a - (m1 + 2))]);
            r.w = fmaf(a01.w, ATT_SCALE, bias_s[abs(ng_a - (m1 + 3))]);
            *(float4*)&s_s[n_a * 1028 + m1] = r;
            r.x = fmaf(a10.x, ATT_SCALE, bias_s[abs(ng_b - (m0 + 0))]);
            r.y = fmaf(a10.y, ATT_SCALE, bias_s[abs(ng_b - (m0 + 1))]);
            r.z = fmaf(a10.z, ATT_SCALE, bias_s[abs(ng_b - (m0 + 2))]);
            r.w = fmaf(a10.w, ATT_SCALE, bias_s[abs(ng_b - (m0 + 3))]);
            *(float4*)&s_s[n_b * 1028 + m0] = r;
            r.x = fmaf(a11.x, ATT_SCALE, bias_s[abs(ng_b - (m1 + 0))]);
            r.y = fmaf(a11.y, ATT_SCALE, bias_s[abs(ng_b - (m1 + 1))]);
            r.z = fmaf(a11.z, ATT_SCALE, bias_s[abs(ng_b - (m1 + 2))]);
            r.w = fmaf(a11.w, ATT_SCALE, bias_s[abs(ng_b - (m1 + 3))]);
            *(float4*)&s_s[n_b * 1028 + m1] = r;
        }
        __syncthreads();
    }

    // ---- phase 3: softmax per row (16 warps x 2 rows) ----
    #pragma unroll
    for (int rr = 0; rr < 2; rr++) {
        int r = wrp * 2 + rr;
        float* row = s_s + r * 1028;
        float mx = -1e30f;
        for (int i = lane * 4; i < RES; i += 128) {
            float4 x = *(const float4*)&row[i];
            mx = fmaxf(mx, fmaxf(fmaxf(x.x, x.y), fmaxf(x.z, x.w)));
        }
        #pragma unroll
        for (int o = 16; o; o >>= 1) mx = fmaxf(mx, __shfl_xor_sync(0xffffffffu, mx, o));
        float sum = 0.0f;
        for (int i = lane * 4; i < RES; i += 128) {
            float4 x = *(const float4*)&row[i];
            x.x = __expf(x.x - mx); x.y = __expf(x.y - mx);
            x.z = __expf(x.z - mx); x.w = __expf(x.w - mx);
            *(float4*)&row[i] = x;
            sum += (x.x + x.y) + (x.z + x.w);
        }
        #pragma unroll
        for (int o = 16; o; o >>= 1) sum += __shfl_xor_sync(0xffffffffu, sum, o);
        if (lane == 0) dsum[r] = 1.0f / sum;
    }
    __syncthreads();

    // ---- phase 4: out[d][n] = sum_m v[d][m] * p[n][m] ----
    const int dg = t & 63;          // rows d = dg and dg+64
    const int nq = (t >> 6) * 4;    // cols nq..nq+3
    float4 oa0 = {0,0,0,0}, oa1 = {0,0,0,0};   // component r = col nq+r
    for (int mt = 0; mt < RES; mt += 128) {
        for (int s = t; s < 4096; s += 512) {
            int d = s >> 5, m4 = (s & 31) * 4;
            *(float4*)&vs[d * 132 + m4] = *(const float4*)&vb[d * RES + mt + m4];
        }
        __syncthreads();
        #pragma unroll 4
        for (int m4 = 0; m4 < 128; m4 += 4) {
            float4 v0 = *(const float4*)&vs[dg * 132 + m4];
            float4 v1 = *(const float4*)&vs[(dg + 64) * 132 + m4];
            float4 p0 = *(const float4*)&s_s[(nq + 0) * 1028 + mt + m4];
            float4 p1 = *(const float4*)&s_s[(nq + 1) * 1028 + mt + m4];
            float4 p2 = *(const float4*)&s_s[(nq + 2) * 1028 + mt + m4];
            float4 p3 = *(const float4*)&s_s[(nq + 3) * 1028 + mt + m4];
            oa0.x = fmaf(v0.x, p0.x, fmaf(v0.y, p0.y, fmaf(v0.z, p0.z, fmaf(v0.w, p0.w, oa0.x))));
            oa0.y = fmaf(v0.x, p1.x, fmaf(v0.y, p1.y, fmaf(v0.z, p1.z, fmaf(v0.w, p1.w, oa0.y))));
            oa0.z = fmaf(v0.x, p2.x, fmaf(v0.y, p2.y, fmaf(v0.z, p2.z, fmaf(v0.w, p2.w, oa0.z))));
            oa0.w = fmaf(v0.x, p3.x, fmaf(v0.y, p3.y, fmaf(v0.z, p3.z, fmaf(v0.w, p3.w, oa0.w))));
            oa1.x = fmaf(v1.x, p0.x, fmaf(v1.y, p0.y, fmaf(v1.z, p0.z, fmaf(v1.w, p0.w, oa1.x))));
            oa1.y = fmaf(v1.x, p1.x, fmaf(v1.y, p1.y, fmaf(v1.z, p1.z, fmaf(v1.w, p1.w, oa1.y))));
            oa1.z = fmaf(v1.x, p2.x, fmaf(v1.y, p2.y, fmaf(v1.z, p2.z, fmaf(v1.w, p2.w, oa1.z))));
            oa1.w = fmaf(v1.x, p3.x, fmaf(v1.y, p3.y, fmaf(v1.z, p3.z, fmaf(v1.w, p3.w, oa1.w))));
        }
        __syncthreads();
    }

    {
        float d0 = dsum[nq + 0], d1 = dsum[nq + 1], d2 = dsum[nq + 2], d3 = dsum[nq + 3];
        float* ob = outp + ((size_t)b * DHDIM + h * DV) * RES + n0;
        float4 w0, w1;
        w0.x = fmaxf(oa0.x * d0, 0.0f); w0.y = fmaxf(oa0.y * d1, 0.0f);
        w0.z = fmaxf(oa0.z * d2, 0.0f); w0.w = fmaxf(oa0.w * d3, 0.0f);
        w1.x = fmaxf(oa1.x * d0, 0.0f); w1.y = fmaxf(oa1.y * d1, 0.0f);
        w1.z = fmaxf(oa1.z * d2, 0.0f); w1.w = fmaxf(oa1.w * d3, 0.0f);
        *(float4*)&ob[(size_t)dg * RES + nq]        = w0;
        *(float4*)&ob[(size_t)(dg + 64) * RES + nq] = w1;
    }
}

// --------------------------------- launch -------------------------------------
extern "C" void kernel_launch(void* const* d_in, const int* in_sizes, int n_in,
                              void* d_out, int out_size)
{
    const float* x      = (const float*)d_in[0];
    const float* w_qkv  = (const float*)d_in[1];
    const float* qkv_g  = (const float*)d_in[2];
    const float* qkv_b  = (const float*)d_in[3];
    const float* qkv_m  = (const float*)d_in[4];
    const float* qkv_v  = (const float*)d_in[5];
    const float* w_dw   = (const float*)d_in[6];
    const float* dw_g   = (const float*)d_in[7];
    const float* dw_b   = (const float*)d_in[8];
    const float* dw_m   = (const float*)d_in[9];
    const float* dw_v   = (const float*)d_in[10];
    const float* w_proj = (const float*)d_in[11];
    const float* proj_g = (const float*)d_in[12];
    const float* proj_b = (const float*)d_in[13];
    const float* proj_m = (const float*)d_in[14];
    const float* proj_v = (const float*)d_in[15];
    const float* att_bias = (const float*)d_in[16];
    // d_in[17] = bias_idxs (== |n-m|, computed inline)

    float *p_qkv, *p_q, *p_att;
    cudaGetSymbolAddress((void**)&p_qkv, g_qkv);
    cudaGetSymbolAddress((void**)&p_q,   g_q);
    cudaGetSymbolAddress((void**)&p_att, g_att);

    cudaFuncSetAttribute(attn_kernel, cudaFuncAttributeMaxDynamicSharedMemorySize,
                         ATTN_SMEM_BYTES);

    // 1) QKV GEMM + BN : (1536 x 512) x (512 x 1024) per batch
    gemm_bn_kernel<<<dim3(RES / 128, HQKV / 128, BATCH), 128>>>(
        w_qkv, x, qkv_g, qkv_b, qkv_m, qkv_v, p_qkv, HQKV, DIMC, RES);

    // 2) depthwise conv + BN on q
    dwconv_bn_kernel<<<(BATCH * NHKD * RES) / 256, 256>>>(
        p_qkv, w_dw, dw_g, dw_b, dw_m, dw_v, p_q);

    // 3) fused attention (logits+bias, softmax, p@v, relu)
    attn_kernel<<<dim3(RES / NT, NHEAD, BATCH), 512, ATTN_SMEM_BYTES>>>(
        p_q, p_qkv, att_bias, p_att);

    // 4) projection GEMM + BN : (512 x 1024) x (1024 x 1024) per batch
    gemm_bn_kernel<<<dim3(RES / 128, DIMC / 128, BATCH), 128>>>(
        w_proj, p_att, proj_g, proj_b, proj_m, proj_v, (float*)d_out,
        DIMC, DHDIM, RES);
}